// round 14
// baseline (speedup 1.0000x reference)
#include <cuda_runtime.h>
#include <cuda_bf16.h>
#include <math.h>
#include <stdint.h>

// Problem constants
#define Bc   4
#define Tc   512
#define Fc   32
#define Dc   128
#define NHc  4
#define HDc  32
#define WINc 64
#define HIDc 512
#define Sc   (Bc*Fc)          // 128 sequences
#define ROWS (Sc*Tc)          // 65536 rows

// ---------------- scratch (device globals; no allocation) ----------------
__device__ float g_y  [ROWS*Dc];        // h2 (Wo gemm EPI 4 output)
__device__ float g_ysum[ROWS];
__device__ float g_w2sum[HIDc];
__device__ float g_b2sum;

__device__ __nv_bfloat16 g_h1bf[ROWS*Dc];
__device__ __nv_bfloat16 g_qkbf[ROWS*Dc];
__device__ __nv_bfloat16 g_QKo [ROWS*2*Dc];
__device__ __nv_bfloat16 g_Vbf [ROWS*Dc];
__device__ __nv_bfloat16 g_Obf [ROWS*Dc];

__device__ __nv_bfloat16 g_Wqkv_bf[3*Dc*Dc];
__device__ __nv_bfloat16 g_Wo_bf  [Dc*Dc];
__device__ __nv_bfloat16 g_W1_bf  [HIDc*Dc];

__device__ __forceinline__ uint32_t smem_u32(const void* p) {
    return (uint32_t)__cvta_generic_to_shared(p);
}
__device__ __forceinline__ void cp16(uint32_t s, const void* g) {
    asm volatile("cp.async.cg.shared.global [%0], [%1], 16;" :: "r"(s), "l"(g));
}

// ---------------- weight prep: bf16 conversion + w2sum/b2sum ----------------
__global__ void conv_weights(const float* __restrict__ Wqkv,
                             const float* __restrict__ Wo,
                             const float* __restrict__ W1,
                             const float* __restrict__ W2,
                             const float* __restrict__ b2) {
    int i = blockIdx.x*blockDim.x + threadIdx.x;
    if (i < 3*Dc*Dc)  g_Wqkv_bf[i] = __float2bfloat16(Wqkv[i]);
    if (i < Dc*Dc)    g_Wo_bf[i]   = __float2bfloat16(Wo[i]);
    if (i < HIDc*Dc)  g_W1_bf[i]   = __float2bfloat16(W1[i]);
    if (i < HIDc) {                     // w2sum[k] = sum_d W2[d,k]
        float s = 0.f;
        #pragma unroll 4
        for (int n = 0; n < Dc; n++) s += W2[n*HIDc + i];
        g_w2sum[i] = s;
    }
    if (i == 0) {
        float s = 0.f;
        for (int d = 0; d < Dc; d++) s += b2[d];
        g_b2sum = s;
    }
}

// ---------------- warp reduce over 32 lanes ----------------
__device__ __forceinline__ float warp_sum(float v) {
    #pragma unroll
    for (int o = 16; o; o >>= 1) v += __shfl_xor_sync(0xffffffffu, v, o);
    return v;
}

// ---------------- K1: LN1 + RoPE (warp-per-row); zero ysum ------------------
__global__ __launch_bounds__(128) void k1_hcf_ln_rope(
        const float* __restrict__ x,
        const float* __restrict__ W_in,
        const float* __restrict__ b_in,
        const float* __restrict__ gamma1,
        const float* __restrict__ beta1) {
    const int warp = threadIdx.x >> 5, lane = threadIdx.x & 31;
    const int row = blockIdx.x*4 + warp;       // s*T + t
    const int s = row >> 9, t = row & (Tc-1);
    const int b = s >> 5, f = s & (Fc-1);
    const int d0 = lane*4;

    float xv = __ldg(&x[(b*Tc + t)*Fc + f]);
    float4 bi = *(const float4*)&b_in[d0];
    float hv[4];
    hv[0] = xv * __ldg(&W_in[(d0+0)*Fc + f]) + bi.x;
    hv[1] = xv * __ldg(&W_in[(d0+1)*Fc + f]) + bi.y;
    hv[2] = xv * __ldg(&W_in[(d0+2)*Fc + f]) + bi.z;
    hv[3] = xv * __ldg(&W_in[(d0+3)*Fc + f]) + bi.w;

    float mean = warp_sum(hv[0]+hv[1]+hv[2]+hv[3]) * (1.f/Dc);
    float dv[4];
    float vs = 0.f;
    #pragma unroll
    for (int i=0;i<4;i++) { dv[i] = hv[i]-mean; vs += dv[i]*dv[i]; }
    float var = warp_sum(vs) * (1.f/Dc);
    float rstd = rsqrtf(var + 1e-5f);

    float4 g4 = *(const float4*)&gamma1[d0];
    float4 be4 = *(const float4*)&beta1[d0];
    float h1[4];
    h1[0] = dv[0]*rstd*g4.x + be4.x;
    h1[1] = dv[1]*rstd*g4.y + be4.y;
    h1[2] = dv[2]*rstd*g4.z + be4.z;
    h1[3] = dv[3]*rstd*g4.w + be4.w;

    size_t base = (size_t)row*Dc + d0;
    __nv_bfloat162 hb[2];
    hb[0] = __floats2bfloat162_rn(h1[0], h1[1]);
    hb[1] = __floats2bfloat162_rn(h1[2], h1[3]);
    *(uint2*)&g_h1bf[base] = *(uint2*)hb;

    // RoPE
    float q[4];
    #pragma unroll
    for (int j=0;j<2;j++) {
        int hd = (d0 + 2*j) & (HDc-1);
        int i2 = hd >> 1;
        float inv = __expf(-(float)(2*i2) * (9.210340371976184f / (float)HDc));
        float fr = (float)t * inv;
        float sn, cs;
        __sincosf(fr, &sn, &cs);
        float e = h1[2*j], o = h1[2*j+1];
        q[2*j]   = e*cs - o*sn;
        q[2*j+1] = e*sn + o*cs;
    }
    __nv_bfloat162 qb[2];
    qb[0] = __floats2bfloat162_rn(q[0], q[1]);
    qb[1] = __floats2bfloat162_rn(q[2], q[3]);
    *(uint2*)&g_qkbf[base] = *(uint2*)qb;

    if (lane == 0) g_ysum[row] = 0.f;   // seed for atomic accumulation
}

// ---------------- bf16 tensor-core GEMM (cp.async double-buffered) -----------
// EPI 3: Cbf = acc+bias (bf16)
// EPI 4: Wo path: h2 = acc + b_o + hcf(recomputed from x,W_in,b_in);
//        Cf = h2 (fp32); ysum += rowsum(h2) (atomic)
#define PKS 40

template<int EPI>
__global__ __launch_bounds__(256) void gemm_bf16(
    const __nv_bfloat16* __restrict__ A,
    const __nv_bfloat16* __restrict__ B,
    const float* __restrict__ bias,
    float* __restrict__ Cf,
    __nv_bfloat16* __restrict__ Cbf,
    int M, int N, int K,
    float* __restrict__ rowsum,
    const float* __restrict__ bin2,   // EPI4: b_in
    const float* __restrict__ xin,    // EPI4: x
    const float* __restrict__ Win)    // EPI4: W_in
{
    __shared__ __nv_bfloat16 As[2][128*PKS];
    __shared__ __nv_bfloat16 Bs[2][64*PKS];
    const int bm = blockIdx.y * 128;
    const int bn = blockIdx.x * 64;
    const int tid  = threadIdx.x;
    const int warp = tid >> 5, lane = tid & 31;
    const int wm = warp >> 1;
    const int wn = warp & 1;

    float acc[2][4][4];
    #pragma unroll
    for (int mi=0;mi<2;mi++)
        #pragma unroll
        for (int ni=0;ni<4;ni++)
            #pragma unroll
            for (int j=0;j<4;j++) acc[mi][ni][j] = 0.f;

    const int lrow = tid >> 2;
    const int lcol = (tid & 3) * 8;
    const int niter = K >> 5;

    cp16(smem_u32(&As[0][lrow*PKS + lcol]),      &A[(size_t)(bm + lrow)*K + lcol]);
    cp16(smem_u32(&As[0][(64+lrow)*PKS + lcol]), &A[(size_t)(bm + 64 + lrow)*K + lcol]);
    cp16(smem_u32(&Bs[0][lrow*PKS + lcol]),      &B[(size_t)(bn + lrow)*K + lcol]);
    asm volatile("cp.async.commit_group;");

    for (int it = 0; it < niter; it++) {
        if (it + 1 < niter) {
            int k0 = (it+1) << 5, st = (it+1) & 1;
            cp16(smem_u32(&As[st][lrow*PKS + lcol]),      &A[(size_t)(bm + lrow)*K + k0 + lcol]);
            cp16(smem_u32(&As[st][(64+lrow)*PKS + lcol]), &A[(size_t)(bm + 64 + lrow)*K + k0 + lcol]);
            cp16(smem_u32(&Bs[st][lrow*PKS + lcol]),      &B[(size_t)(bn + lrow)*K + k0 + lcol]);
            asm volatile("cp.async.commit_group;");
            asm volatile("cp.async.wait_group 1;");
        } else {
            asm volatile("cp.async.wait_group 0;");
        }
        __syncthreads();
        const int cur = it & 1;

        #pragma unroll
        for (int ks = 0; ks < 2; ks++) {
            uint32_t af[2][4], bfr[4][2];
            #pragma unroll
            for (int mi=0;mi<2;mi++) {
                int row = wm*32 + mi*16 + (lane & 15);
                int col = ks*16 + (lane >> 4)*8;
                uint32_t addr = smem_u32(&As[cur][row*PKS + col]);
                asm volatile("ldmatrix.sync.aligned.m8n8.x4.shared.b16 {%0,%1,%2,%3}, [%4];"
                    : "=r"(af[mi][0]),"=r"(af[mi][1]),"=r"(af[mi][2]),"=r"(af[mi][3])
                    : "r"(addr));
            }
            #pragma unroll
            for (int ni=0;ni<4;ni++) {
                int row = wn*32 + ni*8 + (lane & 7);
                int col = ks*16 + ((lane >> 3)&1)*8;
                uint32_t addr = smem_u32(&Bs[cur][row*PKS + col]);
                asm volatile("ldmatrix.sync.aligned.m8n8.x2.shared.b16 {%0,%1}, [%2];"
                    : "=r"(bfr[ni][0]),"=r"(bfr[ni][1]) : "r"(addr));
            }
            #pragma unroll
            for (int mi=0;mi<2;mi++)
                #pragma unroll
                for (int ni=0;ni<4;ni++)
                    asm volatile("mma.sync.aligned.m16n8k16.row.col.f32.bf16.bf16.f32 "
                        "{%0,%1,%2,%3}, {%4,%5,%6,%7}, {%8,%9}, {%0,%1,%2,%3};"
                        : "+f"(acc[mi][ni][0]),"+f"(acc[mi][ni][1]),
                          "+f"(acc[mi][ni][2]),"+f"(acc[mi][ni][3])
                        : "r"(af[mi][0]),"r"(af[mi][1]),"r"(af[mi][2]),"r"(af[mi][3]),
                          "r"(bfr[ni][0]),"r"(bfr[ni][1]));
        }
        __syncthreads();
    }

    // ---------------- epilogue ----------------
    if (EPI == 3) {
        #pragma unroll
        for (int mi=0;mi<2;mi++) {
            int r0 = bm + wm*32 + mi*16 + (lane>>2);
            #pragma unroll
            for (int ni=0;ni<4;ni++) {
                int c = bn + wn*32 + ni*8 + (lane&3)*2;
                float v0 = acc[mi][ni][0] + bias[c];
                float v1 = acc[mi][ni][1] + bias[c+1];
                float v2 = acc[mi][ni][2] + bias[c];
                float v3 = acc[mi][ni][3] + bias[c+1];
                __nv_bfloat162 p0 = __floats2bfloat162_rn(v0, v1);
                __nv_bfloat162 p1 = __floats2bfloat162_rn(v2, v3);
                *(__nv_bfloat162*)&Cbf[(size_t)r0*N + c]     = p0;
                *(__nv_bfloat162*)&Cbf[(size_t)(r0+8)*N + c] = p1;
            }
        }
    } else { // EPI 4
        // block rows all lie within one sequence: b,f block-constant
        const int sB = bm >> 9;
        const int bB = sB >> 5, fB = sB & 31;
        float wN[4][2], addc[4][2];
        #pragma unroll
        for (int ni=0;ni<4;ni++) {
            int c = bn + wn*32 + ni*8 + (lane&3)*2;
            wN[ni][0] = __ldg(&Win[c*Fc + fB]);
            wN[ni][1] = __ldg(&Win[(c+1)*Fc + fB]);
            addc[ni][0] = bias[c]   + bin2[c];
            addc[ni][1] = bias[c+1] + bin2[c+1];
        }
        #pragma unroll
        for (int mi=0;mi<2;mi++) {
            int r0 = bm + wm*32 + mi*16 + (lane>>2);
            int t0 = r0 & (Tc-1);
            float xv0 = __ldg(&xin[(bB*Tc + t0)*Fc + fB]);
            float xv1 = __ldg(&xin[(bB*Tc + t0+8)*Fc + fB]);
            float s0 = 0.f, s1 = 0.f;
            #pragma unroll
            for (int ni=0;ni<4;ni++) {
                int c = bn + wn*32 + ni*8 + (lane&3)*2;
                float v0 = acc[mi][ni][0] + addc[ni][0] + xv0*wN[ni][0];
                float v1 = acc[mi][ni][1] + addc[ni][1] + xv0*wN[ni][1];
                float v2 = acc[mi][ni][2] + addc[ni][0] + xv1*wN[ni][0];
                float v3 = acc[mi][ni][3] + addc[ni][1] + xv1*wN[ni][1];
                *(float2*)&Cf[(size_t)r0*N + c]     = make_float2(v0, v1);
                *(float2*)&Cf[(size_t)(r0+8)*N + c] = make_float2(v2, v3);
                s0 += v0 + v1;
                s1 += v2 + v3;
            }
            s0 += __shfl_xor_sync(0xffffffffu, s0, 1);
            s0 += __shfl_xor_sync(0xffffffffu, s0, 2);
            s1 += __shfl_xor_sync(0xffffffffu, s1, 1);
            s1 += __shfl_xor_sync(0xffffffffu, s1, 2);
            if ((lane&3) == 0) {
                atomicAdd(&rowsum[r0],   s0);
                atomicAdd(&rowsum[r0+8], s1);
            }
        }
    }
}

// ---------------- FFN1 with fused LN2: reads h2 fp32, LN in-kernel ----------
// ysum += rowsum(gelu(LN2(h2) @ W1^T + b1) * w2sum)
#define FKS 136
#define FBS 40

__global__ __launch_bounds__(256) void ffn1_ln(
    const float* __restrict__ h2,
    const __nv_bfloat16* __restrict__ W1b,
    const float* __restrict__ b1,
    const float* __restrict__ gamma2,
    const float* __restrict__ beta2,
    const float* __restrict__ w2s,
    float* __restrict__ rowsum)
{
    __shared__ __nv_bfloat16 As[128*FKS];   // 34.8 KB: normalized h3, full K=128
    __shared__ __nv_bfloat16 Bs[64*FBS];    // 5.1 KB: W1 chunk (32 cols)
    const int bm = blockIdx.y*128, bn = blockIdx.x*64;
    const int tid = threadIdx.x, warp = tid>>5, lane = tid&31;
    const int wm = warp>>1, wn = warp&1;

    // Phase A: LN2 of 16 rows per warp -> As (bf16)
    {
        float4 g4 = *(const float4*)&gamma2[lane*4];
        float4 b4 = *(const float4*)&beta2[lane*4];
        #pragma unroll 4
        for (int rr = 0; rr < 16; rr++) {
            int row = warp*16 + rr;
            float4 hv = *(const float4*)&h2[(size_t)(bm+row)*Dc + lane*4];
            float tot = warp_sum(hv.x+hv.y+hv.z+hv.w);
            float mean = tot * (1.f/Dc);
            float d0 = hv.x-mean, d1 = hv.y-mean, d2 = hv.z-mean, d3 = hv.w-mean;
            float var = warp_sum(d0*d0+d1*d1+d2*d2+d3*d3) * (1.f/Dc);
            float rstd = rsqrtf(var + 1e-5f);
            __nv_bfloat162 o0 = __floats2bfloat162_rn(d0*rstd*g4.x + b4.x, d1*rstd*g4.y + b4.y);
            __nv_bfloat162 o1 = __floats2bfloat162_rn(d2*rstd*g4.z + b4.z, d3*rstd*g4.w + b4.w);
            uint2 pk;
            pk.x = *(uint32_t*)&o0;
            pk.y = *(uint32_t*)&o1;
            *(uint2*)&As[row*FKS + lane*4] = pk;
        }
    }

    float acc[2][4][4];
    #pragma unroll
    for (int mi=0;mi<2;mi++)
        #pragma unroll
        for (int ni=0;ni<4;ni++)
            #pragma unroll
            for (int j=0;j<4;j++) acc[mi][ni][j] = 0.f;

    for (int kc = 0; kc < 4; kc++) {
        __syncthreads();   // As ready (first iter) / Bs consumed (later iters)
        {
            int row = tid >> 2, c4 = (tid & 3) * 8;   // 256 threads = 64 rows x 4
            *(uint4*)&Bs[row*FBS + c4] =
                *(const uint4*)&W1b[(size_t)(bn+row)*Dc + kc*32 + c4];
        }
        __syncthreads();

        #pragma unroll
        for (int ks = 0; ks < 2; ks++) {
            uint32_t af[2][4], bfr[4][2];
            #pragma unroll
            for (int mi=0;mi<2;mi++) {
                int row = wm*32 + mi*16 + (lane & 15);
                int col = kc*32 + ks*16 + (lane >> 4)*8;
                uint32_t addr = smem_u32(&As[row*FKS + col]);
                asm volatile("ldmatrix.sync.aligned.m8n8.x4.shared.b16 {%0,%1,%2,%3}, [%4];"
                    : "=r"(af[mi][0]),"=r"(af[mi][1]),"=r"(af[mi][2]),"=r"(af[mi][3])
                    : "r"(addr));
            }
            #pragma unroll
            for (int ni=0;ni<4;ni++) {
                int row = wn*32 + ni*8 + (lane & 7);
                int col = ks*16 + ((lane >> 3)&1)*8;
                uint32_t addr = smem_u32(&Bs[row*FBS + col]);
                asm volatile("ldmatrix.sync.aligned.m8n8.x2.shared.b16 {%0,%1}, [%2];"
                    : "=r"(bfr[ni][0]),"=r"(bfr[ni][1]) : "r"(addr));
            }
            #pragma unroll
            for (int mi=0;mi<2;mi++)
                #pragma unroll
                for (int ni=0;ni<4;ni++)
                    asm volatile("mma.sync.aligned.m16n8k16.row.col.f32.bf16.bf16.f32 "
                        "{%0,%1,%2,%3}, {%4,%5,%6,%7}, {%8,%9}, {%0,%1,%2,%3};"
                        : "+f"(acc[mi][ni][0]),"+f"(acc[mi][ni][1]),
                          "+f"(acc[mi][ni][2]),"+f"(acc[mi][ni][3])
                        : "r"(af[mi][0]),"r"(af[mi][1]),"r"(af[mi][2]),"r"(af[mi][3]),
                          "r"(bfr[ni][0]),"r"(bfr[ni][1]));
        }
    }

    // epilogue: gelu + w2sum-weighted rowsum -> atomicAdd
    #pragma unroll
    for (int mi=0;mi<2;mi++) {
        float s0 = 0.f, s1 = 0.f;
        #pragma unroll
        for (int ni=0;ni<4;ni++) {
            int c = bn + wn*32 + ni*8 + (lane&3)*2;
            float b0v = b1[c], b1v = b1[c+1];
            float w0 = w2s[c], w1 = w2s[c+1];
            float v0 = acc[mi][ni][0] + b0v;
            float v1 = acc[mi][ni][1] + b1v;
            float v2 = acc[mi][ni][2] + b0v;
            float v3 = acc[mi][ni][3] + b1v;
            v0 = 0.5f*v0*(1.f + erff(v0*0.7071067811865476f));
            v1 = 0.5f*v1*(1.f + erff(v1*0.7071067811865476f));
            v2 = 0.5f*v2*(1.f + erff(v2*0.7071067811865476f));
            v3 = 0.5f*v3*(1.f + erff(v3*0.7071067811865476f));
            s0 += v0*w0 + v1*w1;
            s1 += v2*w0 + v3*w1;
        }
        s0 += __shfl_xor_sync(0xffffffffu, s0, 1);
        s0 += __shfl_xor_sync(0xffffffffu, s0, 2);
        s1 += __shfl_xor_sync(0xffffffffu, s1, 1);
        s1 += __shfl_xor_sync(0xffffffffu, s1, 2);
        if ((lane&3) == 0) {
            int r = bm + wm*32 + mi*16 + (lane>>2);
            atomicAdd(&rowsum[r],   s0);
            atomicAdd(&rowsum[r+8], s1);
        }
    }
}

// ---------------- Attention: tensor-core, windowed causal ----------------
#define QPAD 40

__global__ __launch_bounds__(128) void attn_mma() {
    __shared__ __nv_bfloat16 Qs[64*QPAD];
    __shared__ __nv_bfloat16 Ks[128*QPAD];
    __shared__ __nv_bfloat16 Vs[128*QPAD];   // row-major [key][hd]
    const int qtile = blockIdx.x, h = blockIdx.y, s = blockIdx.z;
    const int q0 = qtile*64;
    const int tid = threadIdx.x, warp = tid>>5, lane = tid&31;

    for (int i = tid; i < 64*4; i += 128) {
        int r = i>>2, c4 = (i&3)*8;
        *(uint4*)&Qs[r*QPAD + c4] =
            *(const uint4*)&g_QKo[(size_t)(s*Tc + q0 + r)*(2*Dc) + h*HDc + c4];
    }
    for (int i = tid; i < 128*4; i += 128) {
        int r = i>>2, c4 = (i&3)*8;
        int kt = q0 - 64 + r;
        uint4 kval = make_uint4(0,0,0,0), vval = make_uint4(0,0,0,0);
        if (kt >= 0) {
            kval = *(const uint4*)&g_QKo[(size_t)(s*Tc + kt)*(2*Dc) + Dc + h*HDc + c4];
            vval = *(const uint4*)&g_Vbf[(size_t)(s*Tc + kt)*Dc + h*HDc + c4];
        }
        *(uint4*)&Ks[r*QPAD + c4] = kval;
        *(uint4*)&Vs[r*QPAD + c4] = vval;
    }
    __syncthreads();

    uint32_t aq[2][4];
    #pragma unroll
    for (int kk=0; kk<2; kk++) {
        int row = warp*16 + (lane & 15);
        int col = kk*16 + (lane >> 4)*8;
        uint32_t addr = smem_u32(&Qs[row*QPAD + col]);
        asm volatile("ldmatrix.sync.aligned.m8n8.x4.shared.b16 {%0,%1,%2,%3}, [%4];"
            : "=r"(aq[kk][0]),"=r"(aq[kk][1]),"=r"(aq[kk][2]),"=r"(aq[kk][3])
            : "r"(addr));
    }

    float sc[16][4];
    #pragma unroll
    for (int ni=0; ni<16; ni++) { sc[ni][0]=sc[ni][1]=sc[ni][2]=sc[ni][3]=0.f; }
    #pragma unroll
    for (int ni=0; ni<16; ni++) {
        #pragma unroll
        for (int kk=0; kk<2; kk++) {
            uint32_t b0, b1;
            int row = ni*8 + (lane & 7);
            int col = kk*16 + ((lane >> 3)&1)*8;
            uint32_t addr = smem_u32(&Ks[row*QPAD + col]);
            asm volatile("ldmatrix.sync.aligned.m8n8.x2.shared.b16 {%0,%1}, [%2];"
                : "=r"(b0),"=r"(b1) : "r"(addr));
            asm volatile("mma.sync.aligned.m16n8k16.row.col.f32.bf16.bf16.f32 "
                "{%0,%1,%2,%3}, {%4,%5,%6,%7}, {%8,%9}, {%0,%1,%2,%3};"
                : "+f"(sc[ni][0]),"+f"(sc[ni][1]),"+f"(sc[ni][2]),"+f"(sc[ni][3])
                : "r"(aq[kk][0]),"r"(aq[kk][1]),"r"(aq[kk][2]),"r"(aq[kk][3]),
                  "r"(b0),"r"(b1));
        }
    }

    const float scale = 0.17677669529663687f;
    const int g = lane >> 2, t4 = lane & 3;
    const int qg0 = q0 + warp*16 + g;
    const int qg1 = qg0 + 8;
    float mx0 = -INFINITY, mx1 = -INFINITY;
    #pragma unroll
    for (int ni=0; ni<16; ni++) {
        #pragma unroll
        for (int j=0; j<2; j++) {
            int col = ni*8 + 2*t4 + j;
            int kg = q0 - 64 + col;
            float v0 = sc[ni][j]   * scale;
            float v1 = sc[ni][2+j] * scale;
            bool ok0 = (kg >= 0) && (kg <= qg0) && (qg0 - kg <= WINc);
            bool ok1 = (kg >= 0) && (kg <= qg1) && (qg1 - kg <= WINc);
            sc[ni][j]   = ok0 ? v0 : -INFINITY;
            sc[ni][2+j] = ok1 ? v1 : -INFINITY;
            mx0 = fmaxf(mx0, sc[ni][j]);
            mx1 = fmaxf(mx1, sc[ni][2+j]);
        }
    }
    mx0 = fmaxf(mx0, __shfl_xor_sync(0xffffffffu, mx0, 1));
    mx0 = fmaxf(mx0, __shfl_xor_sync(0xffffffffu, mx0, 2));
    mx1 = fmaxf(mx1, __shfl_xor_sync(0xffffffffu, mx1, 1));
    mx1 = fmaxf(mx1, __shfl_xor_sync(0xffffffffu, mx1, 2));
    float sum0 = 0.f, sum1 = 0.f;
    #pragma unroll
    for (int ni=0; ni<16; ni++) {
        #pragma unroll
        for (int j=0; j<2; j++) {
            float e0 = (sc[ni][j]   > -INFINITY) ? __expf(sc[ni][j]   - mx0) : 0.f;
            float e1 = (sc[ni][2+j] > -INFINITY) ? __expf(sc[ni][2+j] - mx1) : 0.f;
            sc[ni][j] = e0; sc[ni][2+j] = e1;
            sum0 += e0; sum1 += e1;
        }
    }
    sum0 += __shfl_xor_sync(0xffffffffu, sum0, 1);
    sum0 += __shfl_xor_sync(0xffffffffu, sum0, 2);
    sum1 += __shfl_xor_sync(0xffffffffu, sum1, 1);
    sum1 += __shfl_xor_sync(0xffffffffu, sum1, 2);
    float inv0 = 1.f/sum0, inv1 = 1.f/sum1;

    uint32_t pa[8][4];
    #pragma unroll
    for (int kt8=0; kt8<8; kt8++) {
        __nv_bfloat162 t0 = __floats2bfloat162_rn(sc[2*kt8][0]*inv0,   sc[2*kt8][1]*inv0);
        __nv_bfloat162 t1 = __floats2bfloat162_rn(sc[2*kt8][2]*inv1,   sc[2*kt8][3]*inv1);
        __nv_bfloat162 t2 = __floats2bfloat162_rn(sc[2*kt8+1][0]*inv0, sc[2*kt8+1][1]*inv0);
        __nv_bfloat162 t3 = __floats2bfloat162_rn(sc[2*kt8+1][2]*inv1, sc[2*kt8+1][3]*inv1);
        pa[kt8][0] = *(uint32_t*)&t0;
        pa[kt8][1] = *(uint32_t*)&t1;
        pa[kt8][2] = *(uint32_t*)&t2;
        pa[kt8][3] = *(uint32_t*)&t3;
    }

    float oacc[4][4];
    #pragma unroll
    for (int ni=0; ni<4; ni++) { oacc[ni][0]=oacc[ni][1]=oacc[ni][2]=oacc[ni][3]=0.f; }
    #pragma unroll
    for (int kt8=0; kt8<8; kt8++) {
        #pragma unroll
        for (int ni=0; ni<4; ni++) {
            uint32_t b0, b1;
            int row = kt8*16 + ((lane >> 3)&1)*8 + (lane & 7);
            int col = ni*8;
            uint32_t addr = smem_u32(&Vs[row*QPAD + col]);
            asm volatile("ldmatrix.sync.aligned.m8n8.x2.trans.shared.b16 {%0,%1}, [%2];"
                : "=r"(b0),"=r"(b1) : "r"(addr));
            asm volatile("mma.sync.aligned.m16n8k16.row.col.f32.bf16.bf16.f32 "
                "{%0,%1,%2,%3}, {%4,%5,%6,%7}, {%8,%9}, {%0,%1,%2,%3};"
                : "+f"(oacc[ni][0]),"+f"(oacc[ni][1]),"+f"(oacc[ni][2]),"+f"(oacc[ni][3])
                : "r"(pa[kt8][0]),"r"(pa[kt8][1]),"r"(pa[kt8][2]),"r"(pa[kt8][3]),
                  "r"(b0),"r"(b1));
        }
    }

    #pragma unroll
    for (int ni=0; ni<4; ni++) {
        int col = ni*8 + 2*t4;
        __nv_bfloat162 p0 = __floats2bfloat162_rn(oacc[ni][0], oacc[ni][1]);
        __nv_bfloat162 p1 = __floats2bfloat162_rn(oacc[ni][2], oacc[ni][3]);
        *(__nv_bfloat162*)&g_Obf[(size_t)(s*Tc + qg0)*Dc + h*HDc + col] = p0;
        *(__nv_bfloat162*)&g_Obf[(size_t)(s*Tc + qg1)*Dc + h*HDc + col] = p1;
    }
}

// ---------------- K7: final combine ----------------
__global__ void k7_final(const float* __restrict__ x,
                         const float* __restrict__ W_in,
                         const float* __restrict__ b_in,
                         const float* __restrict__ W_out,
                         const float* __restrict__ b_out,
                         float* __restrict__ out) {
    __shared__ float xs[Fc];
    __shared__ float xw[Dc];
    int bt = blockIdx.x;               // b*T + t
    int tid = threadIdx.x;             // 128
    if (tid < Fc) xs[tid] = x[bt*Fc + tid];
    __syncthreads();
    float acc = b_in[tid];
    #pragma unroll
    for (int f=0; f<Fc; f++) acc += xs[f]*W_in[tid*Fc + f];
    xw[tid] = acc;
    __syncthreads();
    if (tid < Fc) {
        float yp = b_out[tid];
        for (int dd=0; dd<Dc; dd++) yp += xw[dd]*W_out[tid*Dc + dd];
        int b = bt >> 9, t = bt & (Tc-1);
        int srow = (b*Fc + tid)*Tc + t;
        float ymean = (g_ysum[srow] + g_b2sum) * (1.f/(float)Dc);
        out[bt*Fc + tid] = xs[tid] + ymean + yp;
    }
}

// ---------------- launcher ----------------
extern "C" void kernel_launch(void* const* d_in, const int* in_sizes, int n_in,
                              void* d_out, int out_size) {
    const float* x      = (const float*)d_in[0];
    const float* W_in   = (const float*)d_in[1];
    const float* b_in   = (const float*)d_in[2];
    const float* gamma1 = (const float*)d_in[3];
    const float* beta1  = (const float*)d_in[4];
    const float* gamma2 = (const float*)d_in[5];
    const float* beta2  = (const float*)d_in[6];
    const float* W_qkv  = (const float*)d_in[7];
    const float* b_qkv  = (const float*)d_in[8];
    const float* W_o    = (const float*)d_in[9];
    const float* b_o    = (const float*)d_in[10];
    const float* W1     = (const float*)d_in[11];
    const float* b1     = (const float*)d_in[12];
    const float* W2     = (const float*)d_in[13];
    const float* b2     = (const float*)d_in[14];
    const float* W_out  = (const float*)d_in[15];
    const float* b_out  = (const float*)d_in[16];
    float* out = (float*)d_out;

    float *p_y, *p_ysum, *p_w2sum;
    __nv_bfloat16 *p_h1bf, *p_qkbf, *p_QKo, *p_Vbf, *p_Obf;
    __nv_bfloat16 *p_Wqkv, *p_Wo, *p_W1;
    cudaGetSymbolAddress((void**)&p_y,    g_y);
    cudaGetSymbolAddress((void**)&p_ysum, g_ysum);
    cudaGetSymbolAddress((void**)&p_w2sum,g_w2sum);
    cudaGetSymbolAddress((void**)&p_h1bf, g_h1bf);
    cudaGetSymbolAddress((void**)&p_qkbf, g_qkbf);
    cudaGetSymbolAddress((void**)&p_QKo,  g_QKo);
    cudaGetSymbolAddress((void**)&p_Vbf,  g_Vbf);
    cudaGetSymbolAddress((void**)&p_Obf,  g_Obf);
    cudaGetSymbolAddress((void**)&p_Wqkv, g_Wqkv_bf);
    cudaGetSymbolAddress((void**)&p_Wo,   g_Wo_bf);
    cudaGetSymbolAddress((void**)&p_W1,   g_W1_bf);

    // 0) weights -> bf16 ; w2sum/b2sum
    conv_weights<<<(HIDc*Dc + 255)/256, 256>>>(W_qkv, W_o, W1, W2, b2);
    // 1) LN1 + RoPE ; zero ysum
    k1_hcf_ln_rope<<<ROWS/4, 128>>>(x, W_in, b_in, gamma1, beta1);
    // 2) Q,K -> bf16   (N=256)
    gemm_bf16<3><<<dim3(4, ROWS/128), 256>>>(p_qkbf, p_Wqkv, b_qkv, nullptr, p_QKo, ROWS, 256, 128, nullptr, nullptr, nullptr, nullptr);
    // 3) V -> bf16     (N=128)
    gemm_bf16<3><<<dim3(2, ROWS/128), 256>>>(p_h1bf, p_Wqkv + 2*Dc*Dc, b_qkv + 2*Dc, nullptr, p_Vbf, ROWS, 128, 128, nullptr, nullptr, nullptr, nullptr);
    // 4) attention
    attn_mma<<<dim3(Tc/64, NHc, Sc), 128>>>();
    // 5) h2 = O@Wo^T + b_o + hcf(recomputed); ysum += rowsum(h2)
    gemm_bf16<4><<<dim3(2, ROWS/128), 256>>>(p_Obf, p_Wo, b_o, p_y, nullptr, ROWS, 128, 128, p_ysum, b_in, x, W_in);
    // 6) FFN1 with fused LN2: ysum += rowsum(gelu(LN2(h2)@W1^T+b1)*w2sum)
    ffn1_ln<<<dim3(8, ROWS/128), 256>>>(p_y, p_W1, b1, gamma2, beta2, p_w2sum, p_ysum);
    // 7) final combine (adds b2sum)
    k7_final<<<Bc*Tc, 128>>>(x, W_in, b_in, W_out, b_out, out);
}

// round 15
// speedup vs baseline: 1.5439x; 1.5439x over previous
#include <cuda_runtime.h>
#include <cuda_bf16.h>
#include <math.h>
#include <stdint.h>

// Problem constants
#define Bc   4
#define Tc   512
#define Fc   32
#define Dc   128
#define NHc  4
#define HDc  32
#define WINc 64
#define HIDc 512
#define Sc   (Bc*Fc)          // 128 sequences
#define ROWS (Sc*Tc)          // 65536 rows

// ---------------- scratch (device globals; no allocation) ----------------
__device__ float g_y  [ROWS*Dc];        // h2 (Wo gemm EPI 4 output)
__device__ float g_ysum[ROWS];
__device__ float g_w2sum[HIDc];
__device__ float g_b2sum;

__device__ __nv_bfloat16 g_h1bf[ROWS*Dc];
__device__ __nv_bfloat16 g_qkbf[ROWS*Dc];
__device__ __nv_bfloat16 g_QKo [ROWS*2*Dc];
__device__ __nv_bfloat16 g_Vbf [ROWS*Dc];
__device__ __nv_bfloat16 g_Obf [ROWS*Dc];

__device__ __nv_bfloat16 g_Wqkv_bf[3*Dc*Dc];
__device__ __nv_bfloat16 g_Wo_bf  [Dc*Dc];
__device__ __nv_bfloat16 g_W1_bf  [HIDc*Dc];

__device__ __forceinline__ uint32_t smem_u32(const void* p) {
    return (uint32_t)__cvta_generic_to_shared(p);
}
__device__ __forceinline__ void cp16(uint32_t s, const void* g) {
    asm volatile("cp.async.cg.shared.global [%0], [%1], 16;" :: "r"(s), "l"(g));
}

// ---------------- weight prep: bf16 conversion + w2sum/b2sum ----------------
__global__ void conv_weights(const float* __restrict__ Wqkv,
                             const float* __restrict__ Wo,
                             const float* __restrict__ W1,
                             const float* __restrict__ W2,
                             const float* __restrict__ b2) {
    int i = blockIdx.x*blockDim.x + threadIdx.x;
    if (i < 3*Dc*Dc)  g_Wqkv_bf[i] = __float2bfloat16(Wqkv[i]);
    if (i < Dc*Dc)    g_Wo_bf[i]   = __float2bfloat16(Wo[i]);
    if (i < HIDc*Dc)  g_W1_bf[i]   = __float2bfloat16(W1[i]);
    if (i < HIDc) {                     // w2sum[k] = sum_d W2[d,k]
        float s = 0.f;
        #pragma unroll 4
        for (int n = 0; n < Dc; n++) s += W2[n*HIDc + i];
        g_w2sum[i] = s;
    }
    if (i == 0) {
        float s = 0.f;
        for (int d = 0; d < Dc; d++) s += b2[d];
        g_b2sum = s;
    }
}

// ---------------- warp reduce over 32 lanes ----------------
__device__ __forceinline__ float warp_sum(float v) {
    #pragma unroll
    for (int o = 16; o; o >>= 1) v += __shfl_xor_sync(0xffffffffu, v, o);
    return v;
}

// ---------------- K1: LN1 + RoPE (warp-per-row); zero ysum ------------------
__global__ __launch_bounds__(128) void k1_hcf_ln_rope(
        const float* __restrict__ x,
        const float* __restrict__ W_in,
        const float* __restrict__ b_in,
        const float* __restrict__ gamma1,
        const float* __restrict__ beta1) {
    const int warp = threadIdx.x >> 5, lane = threadIdx.x & 31;
    const int row = blockIdx.x*4 + warp;       // s*T + t
    const int s = row >> 9, t = row & (Tc-1);
    const int b = s >> 5, f = s & (Fc-1);
    const int d0 = lane*4;

    float xv = __ldg(&x[(b*Tc + t)*Fc + f]);
    float4 bi = *(const float4*)&b_in[d0];
    float hv[4];
    hv[0] = xv * __ldg(&W_in[(d0+0)*Fc + f]) + bi.x;
    hv[1] = xv * __ldg(&W_in[(d0+1)*Fc + f]) + bi.y;
    hv[2] = xv * __ldg(&W_in[(d0+2)*Fc + f]) + bi.z;
    hv[3] = xv * __ldg(&W_in[(d0+3)*Fc + f]) + bi.w;

    float mean = warp_sum(hv[0]+hv[1]+hv[2]+hv[3]) * (1.f/Dc);
    float dv[4];
    float vs = 0.f;
    #pragma unroll
    for (int i=0;i<4;i++) { dv[i] = hv[i]-mean; vs += dv[i]*dv[i]; }
    float var = warp_sum(vs) * (1.f/Dc);
    float rstd = rsqrtf(var + 1e-5f);

    float4 g4 = *(const float4*)&gamma1[d0];
    float4 be4 = *(const float4*)&beta1[d0];
    float h1[4];
    h1[0] = dv[0]*rstd*g4.x + be4.x;
    h1[1] = dv[1]*rstd*g4.y + be4.y;
    h1[2] = dv[2]*rstd*g4.z + be4.z;
    h1[3] = dv[3]*rstd*g4.w + be4.w;

    size_t base = (size_t)row*Dc + d0;
    __nv_bfloat162 hb[2];
    hb[0] = __floats2bfloat162_rn(h1[0], h1[1]);
    hb[1] = __floats2bfloat162_rn(h1[2], h1[3]);
    *(uint2*)&g_h1bf[base] = *(uint2*)hb;

    // RoPE
    float q[4];
    #pragma unroll
    for (int j=0;j<2;j++) {
        int hd = (d0 + 2*j) & (HDc-1);
        int i2 = hd >> 1;
        float inv = __expf(-(float)(2*i2) * (9.210340371976184f / (float)HDc));
        float fr = (float)t * inv;
        float sn, cs;
        __sincosf(fr, &sn, &cs);
        float e = h1[2*j], o = h1[2*j+1];
        q[2*j]   = e*cs - o*sn;
        q[2*j+1] = e*sn + o*cs;
    }
    __nv_bfloat162 qb[2];
    qb[0] = __floats2bfloat162_rn(q[0], q[1]);
    qb[1] = __floats2bfloat162_rn(q[2], q[3]);
    *(uint2*)&g_qkbf[base] = *(uint2*)qb;

    if (lane == 0) g_ysum[row] = 0.f;   // seed for atomic accumulation
}

// ---------------- bf16 tensor-core GEMM (cp.async double-buffered) -----------
// EPI 3: Cbf = acc+bias (bf16)
// EPI 4: Wo path: h2 = acc + b_o + hcf(recomputed from x,W_in,b_in);
//        Cf = h2 (fp32); ysum += rowsum(h2) (atomic)
#define PKS 40

template<int EPI>
__global__ __launch_bounds__(256) void gemm_bf16(
    const __nv_bfloat16* __restrict__ A,
    const __nv_bfloat16* __restrict__ B,
    const float* __restrict__ bias,
    float* __restrict__ Cf,
    __nv_bfloat16* __restrict__ Cbf,
    int M, int N, int K,
    float* __restrict__ rowsum,
    const float* __restrict__ bin2,   // EPI4: b_in
    const float* __restrict__ xin,    // EPI4: x
    const float* __restrict__ Win)    // EPI4: W_in
{
    __shared__ __nv_bfloat16 As[2][128*PKS];
    __shared__ __nv_bfloat16 Bs[2][64*PKS];
    const int bm = blockIdx.y * 128;
    const int bn = blockIdx.x * 64;
    const int tid  = threadIdx.x;
    const int warp = tid >> 5, lane = tid & 31;
    const int wm = warp >> 1;
    const int wn = warp & 1;

    float acc[2][4][4];
    #pragma unroll
    for (int mi=0;mi<2;mi++)
        #pragma unroll
        for (int ni=0;ni<4;ni++)
            #pragma unroll
            for (int j=0;j<4;j++) acc[mi][ni][j] = 0.f;

    const int lrow = tid >> 2;
    const int lcol = (tid & 3) * 8;
    const int niter = K >> 5;

    cp16(smem_u32(&As[0][lrow*PKS + lcol]),      &A[(size_t)(bm + lrow)*K + lcol]);
    cp16(smem_u32(&As[0][(64+lrow)*PKS + lcol]), &A[(size_t)(bm + 64 + lrow)*K + lcol]);
    cp16(smem_u32(&Bs[0][lrow*PKS + lcol]),      &B[(size_t)(bn + lrow)*K + lcol]);
    asm volatile("cp.async.commit_group;");

    for (int it = 0; it < niter; it++) {
        if (it + 1 < niter) {
            int k0 = (it+1) << 5, st = (it+1) & 1;
            cp16(smem_u32(&As[st][lrow*PKS + lcol]),      &A[(size_t)(bm + lrow)*K + k0 + lcol]);
            cp16(smem_u32(&As[st][(64+lrow)*PKS + lcol]), &A[(size_t)(bm + 64 + lrow)*K + k0 + lcol]);
            cp16(smem_u32(&Bs[st][lrow*PKS + lcol]),      &B[(size_t)(bn + lrow)*K + k0 + lcol]);
            asm volatile("cp.async.commit_group;");
            asm volatile("cp.async.wait_group 1;");
        } else {
            asm volatile("cp.async.wait_group 0;");
        }
        __syncthreads();
        const int cur = it & 1;

        #pragma unroll
        for (int ks = 0; ks < 2; ks++) {
            uint32_t af[2][4], bfr[4][2];
            #pragma unroll
            for (int mi=0;mi<2;mi++) {
                int row = wm*32 + mi*16 + (lane & 15);
                int col = ks*16 + (lane >> 4)*8;
                uint32_t addr = smem_u32(&As[cur][row*PKS + col]);
                asm volatile("ldmatrix.sync.aligned.m8n8.x4.shared.b16 {%0,%1,%2,%3}, [%4];"
                    : "=r"(af[mi][0]),"=r"(af[mi][1]),"=r"(af[mi][2]),"=r"(af[mi][3])
                    : "r"(addr));
            }
            #pragma unroll
            for (int ni=0;ni<4;ni++) {
                int row = wn*32 + ni*8 + (lane & 7);
                int col = ks*16 + ((lane >> 3)&1)*8;
                uint32_t addr = smem_u32(&Bs[cur][row*PKS + col]);
                asm volatile("ldmatrix.sync.aligned.m8n8.x2.shared.b16 {%0,%1}, [%2];"
                    : "=r"(bfr[ni][0]),"=r"(bfr[ni][1]) : "r"(addr));
            }
            #pragma unroll
            for (int mi=0;mi<2;mi++)
                #pragma unroll
                for (int ni=0;ni<4;ni++)
                    asm volatile("mma.sync.aligned.m16n8k16.row.col.f32.bf16.bf16.f32 "
                        "{%0,%1,%2,%3}, {%4,%5,%6,%7}, {%8,%9}, {%0,%1,%2,%3};"
                        : "+f"(acc[mi][ni][0]),"+f"(acc[mi][ni][1]),
                          "+f"(acc[mi][ni][2]),"+f"(acc[mi][ni][3])
                        : "r"(af[mi][0]),"r"(af[mi][1]),"r"(af[mi][2]),"r"(af[mi][3]),
                          "r"(bfr[ni][0]),"r"(bfr[ni][1]));
        }
        __syncthreads();
    }

    // ---------------- epilogue ----------------
    if (EPI == 3) {
        #pragma unroll
        for (int mi=0;mi<2;mi++) {
            int r0 = bm + wm*32 + mi*16 + (lane>>2);
            #pragma unroll
            for (int ni=0;ni<4;ni++) {
                int c = bn + wn*32 + ni*8 + (lane&3)*2;
                float v0 = acc[mi][ni][0] + bias[c];
                float v1 = acc[mi][ni][1] + bias[c+1];
                float v2 = acc[mi][ni][2] + bias[c];
                float v3 = acc[mi][ni][3] + bias[c+1];
                __nv_bfloat162 p0 = __floats2bfloat162_rn(v0, v1);
                __nv_bfloat162 p1 = __floats2bfloat162_rn(v2, v3);
                *(__nv_bfloat162*)&Cbf[(size_t)r0*N + c]     = p0;
                *(__nv_bfloat162*)&Cbf[(size_t)(r0+8)*N + c] = p1;
            }
        }
    } else { // EPI 4
        // block rows all lie within one sequence: b,f block-constant
        const int sB = bm >> 9;
        const int bB = sB >> 5, fB = sB & 31;
        float wN[4][2], addc[4][2];
        #pragma unroll
        for (int ni=0;ni<4;ni++) {
            int c = bn + wn*32 + ni*8 + (lane&3)*2;
            wN[ni][0] = __ldg(&Win[c*Fc + fB]);
            wN[ni][1] = __ldg(&Win[(c+1)*Fc + fB]);
            addc[ni][0] = bias[c]   + bin2[c];
            addc[ni][1] = bias[c+1] + bin2[c+1];
        }
        #pragma unroll
        for (int mi=0;mi<2;mi++) {
            int r0 = bm + wm*32 + mi*16 + (lane>>2);
            int t0 = r0 & (Tc-1);
            float xv0 = __ldg(&xin[(bB*Tc + t0)*Fc + fB]);
            float xv1 = __ldg(&xin[(bB*Tc + t0+8)*Fc + fB]);
            float s0 = 0.f, s1 = 0.f;
            #pragma unroll
            for (int ni=0;ni<4;ni++) {
                int c = bn + wn*32 + ni*8 + (lane&3)*2;
                float v0 = acc[mi][ni][0] + addc[ni][0] + xv0*wN[ni][0];
                float v1 = acc[mi][ni][1] + addc[ni][1] + xv0*wN[ni][1];
                float v2 = acc[mi][ni][2] + addc[ni][0] + xv1*wN[ni][0];
                float v3 = acc[mi][ni][3] + addc[ni][1] + xv1*wN[ni][1];
                *(float2*)&Cf[(size_t)r0*N + c]     = make_float2(v0, v1);
                *(float2*)&Cf[(size_t)(r0+8)*N + c] = make_float2(v2, v3);
                s0 += v0 + v1;
                s1 += v2 + v3;
            }
            s0 += __shfl_xor_sync(0xffffffffu, s0, 1);
            s0 += __shfl_xor_sync(0xffffffffu, s0, 2);
            s1 += __shfl_xor_sync(0xffffffffu, s1, 1);
            s1 += __shfl_xor_sync(0xffffffffu, s1, 2);
            if ((lane&3) == 0) {
                atomicAdd(&rowsum[r0],   s0);
                atomicAdd(&rowsum[r0+8], s1);
            }
        }
    }
}

// ---------------- FFN1 with fused LN2: reads h2 fp32, LN in-kernel ----------
// ysum += rowsum(gelu(LN2(h2) @ W1^T + b1) * w2sum)
#define FKS 136
#define FBS 40

__global__ __launch_bounds__(256) void ffn1_ln(
    const float* __restrict__ h2,
    const __nv_bfloat16* __restrict__ W1b,
    const float* __restrict__ b1,
    const float* __restrict__ gamma2,
    const float* __restrict__ beta2,
    const float* __restrict__ w2s,
    float* __restrict__ rowsum)
{
    __shared__ __nv_bfloat16 As[128*FKS];   // 34.8 KB: normalized h3, full K=128
    __shared__ __nv_bfloat16 Bs[64*FBS];    // 5.1 KB: W1 chunk (32 cols)
    const int bm = blockIdx.y*128, bn = blockIdx.x*64;
    const int tid = threadIdx.x, warp = tid>>5, lane = tid&31;
    const int wm = warp>>1, wn = warp&1;

    // Phase A: LN2 of 16 rows per warp -> As (bf16)
    {
        float4 g4 = *(const float4*)&gamma2[lane*4];
        float4 b4 = *(const float4*)&beta2[lane*4];
        #pragma unroll 4
        for (int rr = 0; rr < 16; rr++) {
            int row = warp*16 + rr;
            float4 hv = *(const float4*)&h2[(size_t)(bm+row)*Dc + lane*4];
            float tot = warp_sum(hv.x+hv.y+hv.z+hv.w);
            float mean = tot * (1.f/Dc);
            float d0 = hv.x-mean, d1 = hv.y-mean, d2 = hv.z-mean, d3 = hv.w-mean;
            float var = warp_sum(d0*d0+d1*d1+d2*d2+d3*d3) * (1.f/Dc);
            float rstd = rsqrtf(var + 1e-5f);
            __nv_bfloat162 o0 = __floats2bfloat162_rn(d0*rstd*g4.x + b4.x, d1*rstd*g4.y + b4.y);
            __nv_bfloat162 o1 = __floats2bfloat162_rn(d2*rstd*g4.z + b4.z, d3*rstd*g4.w + b4.w);
            uint2 pk;
            pk.x = *(uint32_t*)&o0;
            pk.y = *(uint32_t*)&o1;
            *(uint2*)&As[row*FKS + lane*4] = pk;
        }
    }

    float acc[2][4][4];
    #pragma unroll
    for (int mi=0;mi<2;mi++)
        #pragma unroll
        for (int ni=0;ni<4;ni++)
            #pragma unroll
            for (int j=0;j<4;j++) acc[mi][ni][j] = 0.f;

    for (int kc = 0; kc < 4; kc++) {
        __syncthreads();   // As ready (first iter) / Bs consumed (later iters)
        {
            int row = tid >> 2, c4 = (tid & 3) * 8;   // 256 threads = 64 rows x 4
            *(uint4*)&Bs[row*FBS + c4] =
                *(const uint4*)&W1b[(size_t)(bn+row)*Dc + kc*32 + c4];
        }
        __syncthreads();

        #pragma unroll
        for (int ks = 0; ks < 2; ks++) {
            uint32_t af[2][4], bfr[4][2];
            #pragma unroll
            for (int mi=0;mi<2;mi++) {
                int row = wm*32 + mi*16 + (lane & 15);
                int col = kc*32 + ks*16 + (lane >> 4)*8;
                uint32_t addr = smem_u32(&As[row*FKS + col]);
                asm volatile("ldmatrix.sync.aligned.m8n8.x4.shared.b16 {%0,%1,%2,%3}, [%4];"
                    : "=r"(af[mi][0]),"=r"(af[mi][1]),"=r"(af[mi][2]),"=r"(af[mi][3])
                    : "r"(addr));
            }
            #pragma unroll
            for (int ni=0;ni<4;ni++) {
                int row = wn*32 + ni*8 + (lane & 7);
                int col = ks*16 + ((lane >> 3)&1)*8;
                uint32_t addr = smem_u32(&Bs[row*FBS + col]);
                asm volatile("ldmatrix.sync.aligned.m8n8.x2.shared.b16 {%0,%1}, [%2];"
                    : "=r"(bfr[ni][0]),"=r"(bfr[ni][1]) : "r"(addr));
            }
            #pragma unroll
            for (int mi=0;mi<2;mi++)
                #pragma unroll
                for (int ni=0;ni<4;ni++)
                    asm volatile("mma.sync.aligned.m16n8k16.row.col.f32.bf16.bf16.f32 "
                        "{%0,%1,%2,%3}, {%4,%5,%6,%7}, {%8,%9}, {%0,%1,%2,%3};"
                        : "+f"(acc[mi][ni][0]),"+f"(acc[mi][ni][1]),
                          "+f"(acc[mi][ni][2]),"+f"(acc[mi][ni][3])
                        : "r"(af[mi][0]),"r"(af[mi][1]),"r"(af[mi][2]),"r"(af[mi][3]),
                          "r"(bfr[ni][0]),"r"(bfr[ni][1]));
        }
    }

    // epilogue: gelu + w2sum-weighted rowsum -> atomicAdd
    #pragma unroll
    for (int mi=0;mi<2;mi++) {
        float s0 = 0.f, s1 = 0.f;
        #pragma unroll
        for (int ni=0;ni<4;ni++) {
            int c = bn + wn*32 + ni*8 + (lane&3)*2;
            float b0v = b1[c], b1v = b1[c+1];
            float w0 = w2s[c], w1 = w2s[c+1];
            float v0 = acc[mi][ni][0] + b0v;
            float v1 = acc[mi][ni][1] + b1v;
            float v2 = acc[mi][ni][2] + b0v;
            float v3 = acc[mi][ni][3] + b1v;
            v0 = 0.5f*v0*(1.f + erff(v0*0.7071067811865476f));
            v1 = 0.5f*v1*(1.f + erff(v1*0.7071067811865476f));
            v2 = 0.5f*v2*(1.f + erff(v2*0.7071067811865476f));
            v3 = 0.5f*v3*(1.f + erff(v3*0.7071067811865476f));
            s0 += v0*w0 + v1*w1;
            s1 += v2*w0 + v3*w1;
        }
        s0 += __shfl_xor_sync(0xffffffffu, s0, 1);
        s0 += __shfl_xor_sync(0xffffffffu, s0, 2);
        s1 += __shfl_xor_sync(0xffffffffu, s1, 1);
        s1 += __shfl_xor_sync(0xffffffffu, s1, 2);
        if ((lane&3) == 0) {
            int r = bm + wm*32 + mi*16 + (lane>>2);
            atomicAdd(&rowsum[r],   s0);
            atomicAdd(&rowsum[r+8], s1);
        }
    }
}

// ---------------- Attention: tensor-core, windowed causal ----------------
#define QPAD 40

__global__ __launch_bounds__(128) void attn_mma() {
    __shared__ __nv_bfloat16 Qs[64*QPAD];
    __shared__ __nv_bfloat16 Ks[128*QPAD];
    __shared__ __nv_bfloat16 Vs[128*QPAD];   // row-major [key][hd]
    const int qtile = blockIdx.x, h = blockIdx.y, s = blockIdx.z;
    const int q0 = qtile*64;
    const int tid = threadIdx.x, warp = tid>>5, lane = tid&31;

    for (int i = tid; i < 64*4; i += 128) {
        int r = i>>2, c4 = (i&3)*8;
        *(uint4*)&Qs[r*QPAD + c4] =
            *(const uint4*)&g_QKo[(size_t)(s*Tc + q0 + r)*(2*Dc) + h*HDc + c4];
    }
    for (int i = tid; i < 128*4; i += 128) {
        int r = i>>2, c4 = (i&3)*8;
        int kt = q0 - 64 + r;
        uint4 kval = make_uint4(0,0,0,0), vval = make_uint4(0,0,0,0);
        if (kt >= 0) {
            kval = *(const uint4*)&g_QKo[(size_t)(s*Tc + kt)*(2*Dc) + Dc + h*HDc + c4];
            vval = *(const uint4*)&g_Vbf[(size_t)(s*Tc + kt)*Dc + h*HDc + c4];
        }
        *(uint4*)&Ks[r*QPAD + c4] = kval;
        *(uint4*)&Vs[r*QPAD + c4] = vval;
    }
    __syncthreads();

    uint32_t aq[2][4];
    #pragma unroll
    for (int kk=0; kk<2; kk++) {
        int row = warp*16 + (lane & 15);
        int col = kk*16 + (lane >> 4)*8;
        uint32_t addr = smem_u32(&Qs[row*QPAD + col]);
        asm volatile("ldmatrix.sync.aligned.m8n8.x4.shared.b16 {%0,%1,%2,%3}, [%4];"
            : "=r"(aq[kk][0]),"=r"(aq[kk][1]),"=r"(aq[kk][2]),"=r"(aq[kk][3])
            : "r"(addr));
    }

    float sc[16][4];
    #pragma unroll
    for (int ni=0; ni<16; ni++) { sc[ni][0]=sc[ni][1]=sc[ni][2]=sc[ni][3]=0.f; }
    #pragma unroll
    for (int ni=0; ni<16; ni++) {
        #pragma unroll
        for (int kk=0; kk<2; kk++) {
            uint32_t b0, b1;
            int row = ni*8 + (lane & 7);
            int col = kk*16 + ((lane >> 3)&1)*8;
            uint32_t addr = smem_u32(&Ks[row*QPAD + col]);
            asm volatile("ldmatrix.sync.aligned.m8n8.x2.shared.b16 {%0,%1}, [%2];"
                : "=r"(b0),"=r"(b1) : "r"(addr));
            asm volatile("mma.sync.aligned.m16n8k16.row.col.f32.bf16.bf16.f32 "
                "{%0,%1,%2,%3}, {%4,%5,%6,%7}, {%8,%9}, {%0,%1,%2,%3};"
                : "+f"(sc[ni][0]),"+f"(sc[ni][1]),"+f"(sc[ni][2]),"+f"(sc[ni][3])
                : "r"(aq[kk][0]),"r"(aq[kk][1]),"r"(aq[kk][2]),"r"(aq[kk][3]),
                  "r"(b0),"r"(b1));
        }
    }

    const float scale = 0.17677669529663687f;
    const int g = lane >> 2, t4 = lane & 3;
    const int qg0 = q0 + warp*16 + g;
    const int qg1 = qg0 + 8;
    float mx0 = -INFINITY, mx1 = -INFINITY;
    #pragma unroll
    for (int ni=0; ni<16; ni++) {
        #pragma unroll
        for (int j=0; j<2; j++) {
            int col = ni*8 + 2*t4 + j;
            int kg = q0 - 64 + col;
            float v0 = sc[ni][j]   * scale;
            float v1 = sc[ni][2+j] * scale;
            bool ok0 = (kg >= 0) && (kg <= qg0) && (qg0 - kg <= WINc);
            bool ok1 = (kg >= 0) && (kg <= qg1) && (qg1 - kg <= WINc);
            sc[ni][j]   = ok0 ? v0 : -INFINITY;
            sc[ni][2+j] = ok1 ? v1 : -INFINITY;
            mx0 = fmaxf(mx0, sc[ni][j]);
            mx1 = fmaxf(mx1, sc[ni][2+j]);
        }
    }
    mx0 = fmaxf(mx0, __shfl_xor_sync(0xffffffffu, mx0, 1));
    mx0 = fmaxf(mx0, __shfl_xor_sync(0xffffffffu, mx0, 2));
    mx1 = fmaxf(mx1, __shfl_xor_sync(0xffffffffu, mx1, 1));
    mx1 = fmaxf(mx1, __shfl_xor_sync(0xffffffffu, mx1, 2));
    float sum0 = 0.f, sum1 = 0.f;
    #pragma unroll
    for (int ni=0; ni<16; ni++) {
        #pragma unroll
        for (int j=0; j<2; j++) {
            float e0 = (sc[ni][j]   > -INFINITY) ? __expf(sc[ni][j]   - mx0) : 0.f;
            float e1 = (sc[ni][2+j] > -INFINITY) ? __expf(sc[ni][2+j] - mx1) : 0.f;
            sc[ni][j] = e0; sc[ni][2+j] = e1;
            sum0 += e0; sum1 += e1;
        }
    }
    sum0 += __shfl_xor_sync(0xffffffffu, sum0, 1);
    sum0 += __shfl_xor_sync(0xffffffffu, sum0, 2);
    sum1 += __shfl_xor_sync(0xffffffffu, sum1, 1);
    sum1 += __shfl_xor_sync(0xffffffffu, sum1, 2);
    float inv0 = 1.f/sum0, inv1 = 1.f/sum1;

    uint32_t pa[8][4];
    #pragma unroll
    for (int kt8=0; kt8<8; kt8++) {
        __nv_bfloat162 t0 = __floats2bfloat162_rn(sc[2*kt8][0]*inv0,   sc[2*kt8][1]*inv0);
        __nv_bfloat162 t1 = __floats2bfloat162_rn(sc[2*kt8][2]*inv1,   sc[2*kt8][3]*inv1);
        __nv_bfloat162 t2 = __floats2bfloat162_rn(sc[2*kt8+1][0]*inv0, sc[2*kt8+1][1]*inv0);
        __nv_bfloat162 t3 = __floats2bfloat162_rn(sc[2*kt8+1][2]*inv1, sc[2*kt8+1][3]*inv1);
        pa[kt8][0] = *(uint32_t*)&t0;
        pa[kt8][1] = *(uint32_t*)&t1;
        pa[kt8][2] = *(uint32_t*)&t2;
        pa[kt8][3] = *(uint32_t*)&t3;
    }

    float oacc[4][4];
    #pragma unroll
    for (int ni=0; ni<4; ni++) { oacc[ni][0]=oacc[ni][1]=oacc[ni][2]=oacc[ni][3]=0.f; }
    #pragma unroll
    for (int kt8=0; kt8<8; kt8++) {
        #pragma unroll
        for (int ni=0; ni<4; ni++) {
            uint32_t b0, b1;
            int row = kt8*16 + ((lane >> 3)&1)*8 + (lane & 7);
            int col = ni*8;
            uint32_t addr = smem_u32(&Vs[row*QPAD + col]);
            asm volatile("ldmatrix.sync.aligned.m8n8.x2.trans.shared.b16 {%0,%1}, [%2];"
                : "=r"(b0),"=r"(b1) : "r"(addr));
            asm volatile("mma.sync.aligned.m16n8k16.row.col.f32.bf16.bf16.f32 "
                "{%0,%1,%2,%3}, {%4,%5,%6,%7}, {%8,%9}, {%0,%1,%2,%3};"
                : "+f"(oacc[ni][0]),"+f"(oacc[ni][1]),"+f"(oacc[ni][2]),"+f"(oacc[ni][3])
                : "r"(pa[kt8][0]),"r"(pa[kt8][1]),"r"(pa[kt8][2]),"r"(pa[kt8][3]),
                  "r"(b0),"r"(b1));
        }
    }

    #pragma unroll
    for (int ni=0; ni<4; ni++) {
        int col = ni*8 + 2*t4;
        __nv_bfloat162 p0 = __floats2bfloat162_rn(oacc[ni][0], oacc[ni][1]);
        __nv_bfloat162 p1 = __floats2bfloat162_rn(oacc[ni][2], oacc[ni][3]);
        *(__nv_bfloat162*)&g_Obf[(size_t)(s*Tc + qg0)*Dc + h*HDc + col] = p0;
        *(__nv_bfloat162*)&g_Obf[(size_t)(s*Tc + qg1)*Dc + h*HDc + col] = p1;
    }
}

// ---------------- K7: final combine ----------------
__global__ void k7_final(const float* __restrict__ x,
                         const float* __restrict__ W_in,
                         const float* __restrict__ b_in,
                         const float* __restrict__ W_out,
                         const float* __restrict__ b_out,
                         float* __restrict__ out) {
    __shared__ float xs[Fc];
    __shared__ float xw[Dc];
    int bt = blockIdx.x;               // b*T + t
    int tid = threadIdx.x;             // 128
    if (tid < Fc) xs[tid] = x[bt*Fc + tid];
    __syncthreads();
    float acc = b_in[tid];
    #pragma unroll
    for (int f=0; f<Fc; f++) acc += xs[f]*W_in[tid*Fc + f];
    xw[tid] = acc;
    __syncthreads();
    if (tid < Fc) {
        float yp = b_out[tid];
        for (int dd=0; dd<Dc; dd++) yp += xw[dd]*W_out[tid*Dc + dd];
        int b = bt >> 9, t = bt & (Tc-1);
        int srow = (b*Fc + tid)*Tc + t;
        float ymean = (g_ysum[srow] + g_b2sum) * (1.f/(float)Dc);
        out[bt*Fc + tid] = xs[tid] + ymean + yp;
    }
}

// ---------------- launcher ----------------
extern "C" void kernel_launch(void* const* d_in, const int* in_sizes, int n_in,
                              void* d_out, int out_size) {
    const float* x      = (const float*)d_in[0];
    const float* W_in   = (const float*)d_in[1];
    const float* b_in   = (const float*)d_in[2];
    const float* gamma1 = (const float*)d_in[3];
    const float* beta1  = (const float*)d_in[4];
    const float* gamma2 = (const float*)d_in[5];
    const float* beta2  = (const float*)d_in[6];
    const float* W_qkv  = (const float*)d_in[7];
    const float* b_qkv  = (const float*)d_in[8];
    const float* W_o    = (const float*)d_in[9];
    const float* b_o    = (const float*)d_in[10];
    const float* W1     = (const float*)d_in[11];
    const float* b1     = (const float*)d_in[12];
    const float* W2     = (const float*)d_in[13];
    const float* b2     = (const float*)d_in[14];
    const float* W_out  = (const float*)d_in[15];
    const float* b_out  = (const float*)d_in[16];
    float* out = (float*)d_out;

    float *p_y, *p_ysum, *p_w2sum;
    __nv_bfloat16 *p_h1bf, *p_qkbf, *p_QKo, *p_Vbf, *p_Obf;
    __nv_bfloat16 *p_Wqkv, *p_Wo, *p_W1;
    cudaGetSymbolAddress((void**)&p_y,    g_y);
    cudaGetSymbolAddress((void**)&p_ysum, g_ysum);
    cudaGetSymbolAddress((void**)&p_w2sum,g_w2sum);
    cudaGetSymbolAddress((void**)&p_h1bf, g_h1bf);
    cudaGetSymbolAddress((void**)&p_qkbf, g_qkbf);
    cudaGetSymbolAddress((void**)&p_QKo,  g_QKo);
    cudaGetSymbolAddress((void**)&p_Vbf,  g_Vbf);
    cudaGetSymbolAddress((void**)&p_Obf,  g_Obf);
    cudaGetSymbolAddress((void**)&p_Wqkv, g_Wqkv_bf);
    cudaGetSymbolAddress((void**)&p_Wo,   g_Wo_bf);
    cudaGetSymbolAddress((void**)&p_W1,   g_W1_bf);

    // 0) weights -> bf16 ; w2sum/b2sum
    conv_weights<<<(HIDc*Dc + 255)/256, 256>>>(W_qkv, W_o, W1, W2, b2);
    // 1) LN1 + RoPE ; zero ysum
    k1_hcf_ln_rope<<<ROWS/4, 128>>>(x, W_in, b_in, gamma1, beta1);
    // 2) Q,K -> bf16   (N=256)
    gemm_bf16<3><<<dim3(4, ROWS/128), 256>>>(p_qkbf, p_Wqkv, b_qkv, nullptr, p_QKo, ROWS, 256, 128, nullptr, nullptr, nullptr, nullptr);
    // 3) V -> bf16     (N=128)
    gemm_bf16<3><<<dim3(2, ROWS/128), 256>>>(p_h1bf, p_Wqkv + 2*Dc*Dc, b_qkv + 2*Dc, nullptr, p_Vbf, ROWS, 128, 128, nullptr, nullptr, nullptr, nullptr);
    // 4) attention
    attn_mma<<<dim3(Tc/64, NHc, Sc), 128>>>();
    // 5) h2 = O@Wo^T + b_o + hcf(recomputed); ysum += rowsum(h2)
    gemm_bf16<4><<<dim3(2, ROWS/128), 256>>>(p_Obf, p_Wo, b_o, p_y, nullptr, ROWS, 128, 128, p_ysum, b_in, x, W_in);
    // 6) FFN1 with fused LN2: ysum += rowsum(gelu(LN2(h2)@W1^T+b1)*w2sum)
    ffn1_ln<<<dim3(8, ROWS/128), 256>>>(p_y, p_W1, b1, gamma2, beta2, p_w2sum, p_ysum);
    // 7) final combine (adds b2sum)
    k7_final<<<Bc*Tc, 128>>>(x, W_in, b_in, W_out, b_out, out);
}

// round 16
// speedup vs baseline: 1.5517x; 1.0051x over previous
#include <cuda_runtime.h>
#include <cuda_bf16.h>
#include <math.h>
#include <stdint.h>

// Problem constants
#define Bc   4
#define Tc   512
#define Fc   32
#define Dc   128
#define NHc  4
#define HDc  32
#define WINc 64
#define HIDc 512
#define Sc   (Bc*Fc)          // 128 sequences
#define ROWS (Sc*Tc)          // 65536 rows

// ---------------- scratch (device globals; no allocation) ----------------
__device__ float g_hcf[ROWS*Dc];
__device__ float g_y  [ROWS*Dc];        // h2 (Wo gemm EPI 4 output)
__device__ float g_ysum[ROWS];
__device__ float g_w2sum[HIDc];
__device__ float g_b2sum;

__device__ __nv_bfloat16 g_h1bf[ROWS*Dc];
__device__ __nv_bfloat16 g_qkbf[ROWS*Dc];
__device__ __nv_bfloat16 g_QKo [ROWS*2*Dc];
__device__ __nv_bfloat16 g_Vbf [ROWS*Dc];
__device__ __nv_bfloat16 g_Obf [ROWS*Dc];
__device__ __nv_bfloat16 g_h3bf[ROWS*Dc];

__device__ __nv_bfloat16 g_Wqkv_bf[3*Dc*Dc];
__device__ __nv_bfloat16 g_Wo_bf  [Dc*Dc];
__device__ __nv_bfloat16 g_W1_bf  [HIDc*Dc];

__device__ __forceinline__ uint32_t smem_u32(const void* p) {
    return (uint32_t)__cvta_generic_to_shared(p);
}
__device__ __forceinline__ void cp16(uint32_t s, const void* g) {
    asm volatile("cp.async.cg.shared.global [%0], [%1], 16;" :: "r"(s), "l"(g));
}

// ---------------- weight prep: bf16 conversion + w2sum/b2sum ----------------
__global__ void conv_weights(const float* __restrict__ Wqkv,
                             const float* __restrict__ Wo,
                             const float* __restrict__ W1,
                             const float* __restrict__ W2,
                             const float* __restrict__ b2) {
    int i = blockIdx.x*blockDim.x + threadIdx.x;
    if (i < 3*Dc*Dc)  g_Wqkv_bf[i] = __float2bfloat16(Wqkv[i]);
    if (i < Dc*Dc)    g_Wo_bf[i]   = __float2bfloat16(Wo[i]);
    if (i < HIDc*Dc)  g_W1_bf[i]   = __float2bfloat16(W1[i]);
    if (i < HIDc) {                     // w2sum[k] = sum_d W2[d,k]
        float s = 0.f;
        #pragma unroll 4
        for (int n = 0; n < Dc; n++) s += W2[n*HIDc + i];
        g_w2sum[i] = s;
    }
    if (i == 0) {
        float s = 0.f;
        for (int d = 0; d < Dc; d++) s += b2[d];
        g_b2sum = s;
    }
}

// ---------------- warp reduce over 32 lanes ----------------
__device__ __forceinline__ float warp_sum(float v) {
    #pragma unroll
    for (int o = 16; o; o >>= 1) v += __shfl_xor_sync(0xffffffffu, v, o);
    return v;
}

// ---------------- K1: hcf + LN1 + RoPE  (warp-per-row, no bars) -------------
__global__ __launch_bounds__(128) void k1_hcf_ln_rope(
        const float* __restrict__ x,
        const float* __restrict__ W_in,
        const float* __restrict__ b_in,
        const float* __restrict__ gamma1,
        const float* __restrict__ beta1) {
    const int warp = threadIdx.x >> 5, lane = threadIdx.x & 31;
    const int row = blockIdx.x*4 + warp;       // s*T + t
    const int s = row >> 9, t = row & (Tc-1);
    const int b = s >> 5, f = s & (Fc-1);
    const int d0 = lane*4;

    float xv = __ldg(&x[(b*Tc + t)*Fc + f]);
    float4 bi = *(const float4*)&b_in[d0];
    float hv[4];
    hv[0] = xv * __ldg(&W_in[(d0+0)*Fc + f]) + bi.x;
    hv[1] = xv * __ldg(&W_in[(d0+1)*Fc + f]) + bi.y;
    hv[2] = xv * __ldg(&W_in[(d0+2)*Fc + f]) + bi.z;
    hv[3] = xv * __ldg(&W_in[(d0+3)*Fc + f]) + bi.w;

    float mean = warp_sum(hv[0]+hv[1]+hv[2]+hv[3]) * (1.f/Dc);
    float dv[4];
    float vs = 0.f;
    #pragma unroll
    for (int i=0;i<4;i++) { dv[i] = hv[i]-mean; vs += dv[i]*dv[i]; }
    float var = warp_sum(vs) * (1.f/Dc);
    float rstd = rsqrtf(var + 1e-5f);

    float4 g4 = *(const float4*)&gamma1[d0];
    float4 be4 = *(const float4*)&beta1[d0];
    float h1[4];
    h1[0] = dv[0]*rstd*g4.x + be4.x;
    h1[1] = dv[1]*rstd*g4.y + be4.y;
    h1[2] = dv[2]*rstd*g4.z + be4.z;
    h1[3] = dv[3]*rstd*g4.w + be4.w;

    size_t base = (size_t)row*Dc + d0;
    *(float4*)&g_hcf[base] = make_float4(hv[0],hv[1],hv[2],hv[3]);
    __nv_bfloat162 hb[2];
    hb[0] = __floats2bfloat162_rn(h1[0], h1[1]);
    hb[1] = __floats2bfloat162_rn(h1[2], h1[3]);
    *(uint2*)&g_h1bf[base] = *(uint2*)hb;

    // RoPE
    float q[4];
    #pragma unroll
    for (int j=0;j<2;j++) {
        int hd = (d0 + 2*j) & (HDc-1);
        int i2 = hd >> 1;
        float inv = __expf(-(float)(2*i2) * (9.210340371976184f / (float)HDc));
        float fr = (float)t * inv;
        float sn, cs;
        __sincosf(fr, &sn, &cs);
        float e = h1[2*j], o = h1[2*j+1];
        q[2*j]   = e*cs - o*sn;
        q[2*j+1] = e*sn + o*cs;
    }
    __nv_bfloat162 qb[2];
    qb[0] = __floats2bfloat162_rn(q[0], q[1]);
    qb[1] = __floats2bfloat162_rn(q[2], q[3]);
    *(uint2*)&g_qkbf[base] = *(uint2*)qb;
}

// ---------------- bf16 tensor-core GEMM (cp.async double-buffered) -----------
// EPI 1: gelu(acc+bias)·w2s rowsum -> atomicAdd rowsum[] (no C store)
// EPI 3: Cbf = acc+bias (bf16)
// EPI 4: Cf  = acc+bias+hres (fp32)   [residual-fused]
#define PKS 40

template<int EPI>
__global__ __launch_bounds__(256) void gemm_bf16(
    const __nv_bfloat16* __restrict__ A,
    const __nv_bfloat16* __restrict__ B,
    const float* __restrict__ bias,
    float* __restrict__ Cf,
    __nv_bfloat16* __restrict__ Cbf,
    int M, int N, int K,
    float* __restrict__ rowsum,
    const float* __restrict__ w2s,
    const float* __restrict__ hres)
{
    __shared__ __nv_bfloat16 As[2][128*PKS];
    __shared__ __nv_bfloat16 Bs[2][64*PKS];
    const int bm = blockIdx.y * 128;
    const int bn = blockIdx.x * 64;
    const int tid  = threadIdx.x;
    const int warp = tid >> 5, lane = tid & 31;
    const int wm = warp >> 1;
    const int wn = warp & 1;

    float acc[2][4][4];
    #pragma unroll
    for (int mi=0;mi<2;mi++)
        #pragma unroll
        for (int ni=0;ni<4;ni++)
            #pragma unroll
            for (int j=0;j<4;j++) acc[mi][ni][j] = 0.f;

    const int lrow = tid >> 2;
    const int lcol = (tid & 3) * 8;
    const int niter = K >> 5;

    cp16(smem_u32(&As[0][lrow*PKS + lcol]),      &A[(size_t)(bm + lrow)*K + lcol]);
    cp16(smem_u32(&As[0][(64+lrow)*PKS + lcol]), &A[(size_t)(bm + 64 + lrow)*K + lcol]);
    cp16(smem_u32(&Bs[0][lrow*PKS + lcol]),      &B[(size_t)(bn + lrow)*K + lcol]);
    asm volatile("cp.async.commit_group;");

    for (int it = 0; it < niter; it++) {
        if (it + 1 < niter) {
            int k0 = (it+1) << 5, st = (it+1) & 1;
            cp16(smem_u32(&As[st][lrow*PKS + lcol]),      &A[(size_t)(bm + lrow)*K + k0 + lcol]);
            cp16(smem_u32(&As[st][(64+lrow)*PKS + lcol]), &A[(size_t)(bm + 64 + lrow)*K + k0 + lcol]);
            cp16(smem_u32(&Bs[st][lrow*PKS + lcol]),      &B[(size_t)(bn + lrow)*K + k0 + lcol]);
            asm volatile("cp.async.commit_group;");
            asm volatile("cp.async.wait_group 1;");
        } else {
            asm volatile("cp.async.wait_group 0;");
        }
        __syncthreads();
        const int cur = it & 1;

        #pragma unroll
        for (int ks = 0; ks < 2; ks++) {
            uint32_t af[2][4], bfr[4][2];
            #pragma unroll
            for (int mi=0;mi<2;mi++) {
                int row = wm*32 + mi*16 + (lane & 15);
                int col = ks*16 + (lane >> 4)*8;
                uint32_t addr = smem_u32(&As[cur][row*PKS + col]);
                asm volatile("ldmatrix.sync.aligned.m8n8.x4.shared.b16 {%0,%1,%2,%3}, [%4];"
                    : "=r"(af[mi][0]),"=r"(af[mi][1]),"=r"(af[mi][2]),"=r"(af[mi][3])
                    : "r"(addr));
            }
            #pragma unroll
            for (int ni=0;ni<4;ni++) {
                int row = wn*32 + ni*8 + (lane & 7);
                int col = ks*16 + ((lane >> 3)&1)*8;
                uint32_t addr = smem_u32(&Bs[cur][row*PKS + col]);
                asm volatile("ldmatrix.sync.aligned.m8n8.x2.shared.b16 {%0,%1}, [%2];"
                    : "=r"(bfr[ni][0]),"=r"(bfr[ni][1]) : "r"(addr));
            }
            #pragma unroll
            for (int mi=0;mi<2;mi++)
                #pragma unroll
                for (int ni=0;ni<4;ni++)
                    asm volatile("mma.sync.aligned.m16n8k16.row.col.f32.bf16.bf16.f32 "
                        "{%0,%1,%2,%3}, {%4,%5,%6,%7}, {%8,%9}, {%0,%1,%2,%3};"
                        : "+f"(acc[mi][ni][0]),"+f"(acc[mi][ni][1]),
                          "+f"(acc[mi][ni][2]),"+f"(acc[mi][ni][3])
                        : "r"(af[mi][0]),"r"(af[mi][1]),"r"(af[mi][2]),"r"(af[mi][3]),
                          "r"(bfr[ni][0]),"r"(bfr[ni][1]));
        }
        __syncthreads();
    }

    // ---------------- epilogue ----------------
    if (EPI == 1) {
        #pragma unroll
        for (int mi=0;mi<2;mi++) {
            float s0 = 0.f, s1 = 0.f;
            #pragma unroll
            for (int ni=0;ni<4;ni++) {
                int c = bn + wn*32 + ni*8 + (lane&3)*2;
                float b0v = bias[c], b1v = bias[c+1];
                float w0 = w2s[c],  w1 = w2s[c+1];
                float v0 = acc[mi][ni][0] + b0v;
                float v1 = acc[mi][ni][1] + b1v;
                float v2 = acc[mi][ni][2] + b0v;
                float v3 = acc[mi][ni][3] + b1v;
                v0 = 0.5f*v0*(1.f + erff(v0*0.7071067811865476f));
                v1 = 0.5f*v1*(1.f + erff(v1*0.7071067811865476f));
                v2 = 0.5f*v2*(1.f + erff(v2*0.7071067811865476f));
                v3 = 0.5f*v3*(1.f + erff(v3*0.7071067811865476f));
                s0 += v0*w0 + v1*w1;
                s1 += v2*w0 + v3*w1;
            }
            s0 += __shfl_xor_sync(0xffffffffu, s0, 1);
            s0 += __shfl_xor_sync(0xffffffffu, s0, 2);
            s1 += __shfl_xor_sync(0xffffffffu, s1, 1);
            s1 += __shfl_xor_sync(0xffffffffu, s1, 2);
            if ((lane&3) == 0) {
                int r = bm + wm*32 + mi*16 + (lane>>2);
                atomicAdd(&rowsum[r],   s0);
                atomicAdd(&rowsum[r+8], s1);
            }
        }
    } else {
        #pragma unroll
        for (int mi=0;mi<2;mi++) {
            int r0 = bm + wm*32 + mi*16 + (lane>>2);
            #pragma unroll
            for (int ni=0;ni<4;ni++) {
                int c = bn + wn*32 + ni*8 + (lane&3)*2;
                float v0 = acc[mi][ni][0] + bias[c];
                float v1 = acc[mi][ni][1] + bias[c+1];
                float v2 = acc[mi][ni][2] + bias[c];
                float v3 = acc[mi][ni][3] + bias[c+1];
                if (EPI == 3) {
                    __nv_bfloat162 p0 = __floats2bfloat162_rn(v0, v1);
                    __nv_bfloat162 p1 = __floats2bfloat162_rn(v2, v3);
                    *(__nv_bfloat162*)&Cbf[(size_t)r0*N + c]     = p0;
                    *(__nv_bfloat162*)&Cbf[(size_t)(r0+8)*N + c] = p1;
                } else { // EPI 4: + residual hres
                    float2 h0 = *(const float2*)&hres[(size_t)r0*N + c];
                    float2 h1 = *(const float2*)&hres[(size_t)(r0+8)*N + c];
                    *(float2*)&Cf[(size_t)r0*N + c]     = make_float2(v0+h0.x, v1+h0.y);
                    *(float2*)&Cf[(size_t)(r0+8)*N + c] = make_float2(v2+h1.x, v3+h1.y);
                }
            }
        }
    }
}

// ---------------- Attention: merged qtile-pair, 8 warps, 192-key window -----
#define QPAD 40

__global__ __launch_bounds__(256) void attn_mma() {
    __shared__ __nv_bfloat16 Qs[128*QPAD];
    __shared__ __nv_bfloat16 Ks[192*QPAD];
    __shared__ __nv_bfloat16 Vs[192*QPAD];   // row-major [key][hd]
    const int qpair = blockIdx.x, h = blockIdx.y, s = blockIdx.z;
    const int q0 = qpair*128;                 // queries [q0, q0+128)
    const int tid = threadIdx.x, warp = tid>>5, lane = tid&31;

    // load Q (128 rows)
    for (int i = tid; i < 128*4; i += 256) {
        int r = i>>2, c4 = (i&3)*8;
        *(uint4*)&Qs[r*QPAD + c4] =
            *(const uint4*)&g_QKo[(size_t)(s*Tc + q0 + r)*(2*Dc) + h*HDc + c4];
    }
    // load K/V (192 rows), keys q0-64 .. q0+127
    for (int i = tid; i < 192*4; i += 256) {
        int r = i>>2, c4 = (i&3)*8;
        int kt = q0 - 64 + r;
        uint4 kval = make_uint4(0,0,0,0), vval = make_uint4(0,0,0,0);
        if (kt >= 0 && kt < Tc) {
            kval = *(const uint4*)&g_QKo[(size_t)(s*Tc + kt)*(2*Dc) + Dc + h*HDc + c4];
            vval = *(const uint4*)&g_Vbf[(size_t)(s*Tc + kt)*Dc + h*HDc + c4];
        }
        *(uint4*)&Ks[r*QPAD + c4] = kval;
        *(uint4*)&Vs[r*QPAD + c4] = vval;
    }
    __syncthreads();

    // warp w: queries q0 + w*16 .. +15 ; key slice rows [koff, koff+128)
    const int koff = (warp >= 4) ? 64 : 0;

    uint32_t aq[2][4];
    #pragma unroll
    for (int kk=0; kk<2; kk++) {
        int row = warp*16 + (lane & 15);
        int col = kk*16 + (lane >> 4)*8;
        uint32_t addr = smem_u32(&Qs[row*QPAD + col]);
        asm volatile("ldmatrix.sync.aligned.m8n8.x4.shared.b16 {%0,%1,%2,%3}, [%4];"
            : "=r"(aq[kk][0]),"=r"(aq[kk][1]),"=r"(aq[kk][2]),"=r"(aq[kk][3])
            : "r"(addr));
    }

    float sc[16][4];
    #pragma unroll
    for (int ni=0; ni<16; ni++) { sc[ni][0]=sc[ni][1]=sc[ni][2]=sc[ni][3]=0.f; }
    #pragma unroll
    for (int ni=0; ni<16; ni++) {
        #pragma unroll
        for (int kk=0; kk<2; kk++) {
            uint32_t b0, b1;
            int row = koff + ni*8 + (lane & 7);
            int col = kk*16 + ((lane >> 3)&1)*8;
            uint32_t addr = smem_u32(&Ks[row*QPAD + col]);
            asm volatile("ldmatrix.sync.aligned.m8n8.x2.shared.b16 {%0,%1}, [%2];"
                : "=r"(b0),"=r"(b1) : "r"(addr));
            asm volatile("mma.sync.aligned.m16n8k16.row.col.f32.bf16.bf16.f32 "
                "{%0,%1,%2,%3}, {%4,%5,%6,%7}, {%8,%9}, {%0,%1,%2,%3};"
                : "+f"(sc[ni][0]),"+f"(sc[ni][1]),"+f"(sc[ni][2]),"+f"(sc[ni][3])
                : "r"(aq[kk][0]),"r"(aq[kk][1]),"r"(aq[kk][2]),"r"(aq[kk][3]),
                  "r"(b0),"r"(b1));
        }
    }

    const float scale = 0.17677669529663687f;
    const int g = lane >> 2, t4 = lane & 3;
    const int qg0 = q0 + warp*16 + g;
    const int qg1 = qg0 + 8;
    const int kbase = q0 - 64 + koff;
    float mx0 = -INFINITY, mx1 = -INFINITY;
    #pragma unroll
    for (int ni=0; ni<16; ni++) {
        #pragma unroll
        for (int j=0; j<2; j++) {
            int kg = kbase + ni*8 + 2*t4 + j;
            float v0 = sc[ni][j]   * scale;
            float v1 = sc[ni][2+j] * scale;
            bool ok0 = (kg >= 0) && (kg <= qg0) && (qg0 - kg <= WINc);
            bool ok1 = (kg >= 0) && (kg <= qg1) && (qg1 - kg <= WINc);
            sc[ni][j]   = ok0 ? v0 : -INFINITY;
            sc[ni][2+j] = ok1 ? v1 : -INFINITY;
            mx0 = fmaxf(mx0, sc[ni][j]);
            mx1 = fmaxf(mx1, sc[ni][2+j]);
        }
    }
    mx0 = fmaxf(mx0, __shfl_xor_sync(0xffffffffu, mx0, 1));
    mx0 = fmaxf(mx0, __shfl_xor_sync(0xffffffffu, mx0, 2));
    mx1 = fmaxf(mx1, __shfl_xor_sync(0xffffffffu, mx1, 1));
    mx1 = fmaxf(mx1, __shfl_xor_sync(0xffffffffu, mx1, 2));
    float sum0 = 0.f, sum1 = 0.f;
    #pragma unroll
    for (int ni=0; ni<16; ni++) {
        #pragma unroll
        for (int j=0; j<2; j++) {
            float e0 = (sc[ni][j]   > -INFINITY) ? __expf(sc[ni][j]   - mx0) : 0.f;
            float e1 = (sc[ni][2+j] > -INFINITY) ? __expf(sc[ni][2+j] - mx1) : 0.f;
            sc[ni][j] = e0; sc[ni][2+j] = e1;
            sum0 += e0; sum1 += e1;
        }
    }
    sum0 += __shfl_xor_sync(0xffffffffu, sum0, 1);
    sum0 += __shfl_xor_sync(0xffffffffu, sum0, 2);
    sum1 += __shfl_xor_sync(0xffffffffu, sum1, 1);
    sum1 += __shfl_xor_sync(0xffffffffu, sum1, 2);
    float inv0 = 1.f/sum0, inv1 = 1.f/sum1;

    uint32_t pa[8][4];
    #pragma unroll
    for (int kt8=0; kt8<8; kt8++) {
        __nv_bfloat162 t0 = __floats2bfloat162_rn(sc[2*kt8][0]*inv0,   sc[2*kt8][1]*inv0);
        __nv_bfloat162 t1 = __floats2bfloat162_rn(sc[2*kt8][2]*inv1,   sc[2*kt8][3]*inv1);
        __nv_bfloat162 t2 = __floats2bfloat162_rn(sc[2*kt8+1][0]*inv0, sc[2*kt8+1][1]*inv0);
        __nv_bfloat162 t3 = __floats2bfloat162_rn(sc[2*kt8+1][2]*inv1, sc[2*kt8+1][3]*inv1);
        pa[kt8][0] = *(uint32_t*)&t0;
        pa[kt8][1] = *(uint32_t*)&t1;
        pa[kt8][2] = *(uint32_t*)&t2;
        pa[kt8][3] = *(uint32_t*)&t3;
    }

    float oacc[4][4];
    #pragma unroll
    for (int ni=0; ni<4; ni++) { oacc[ni][0]=oacc[ni][1]=oacc[ni][2]=oacc[ni][3]=0.f; }
    #pragma unroll
    for (int kt8=0; kt8<8; kt8++) {
        #pragma unroll
        for (int ni=0; ni<4; ni++) {
            uint32_t b0, b1;
            int row = koff + kt8*16 + ((lane >> 3)&1)*8 + (lane & 7);
            int col = ni*8;
            uint32_t addr = smem_u32(&Vs[row*QPAD + col]);
            asm volatile("ldmatrix.sync.aligned.m8n8.x2.trans.shared.b16 {%0,%1}, [%2];"
                : "=r"(b0),"=r"(b1) : "r"(addr));
            asm volatile("mma.sync.aligned.m16n8k16.row.col.f32.bf16.bf16.f32 "
                "{%0,%1,%2,%3}, {%4,%5,%6,%7}, {%8,%9}, {%0,%1,%2,%3};"
                : "+f"(oacc[ni][0]),"+f"(oacc[ni][1]),"+f"(oacc[ni][2]),"+f"(oacc[ni][3])
                : "r"(pa[kt8][0]),"r"(pa[kt8][1]),"r"(pa[kt8][2]),"r"(pa[kt8][3]),
                  "r"(b0),"r"(b1));
        }
    }

    #pragma unroll
    for (int ni=0; ni<4; ni++) {
        int col = ni*8 + 2*t4;
        __nv_bfloat162 p0 = __floats2bfloat162_rn(oacc[ni][0], oacc[ni][1]);
        __nv_bfloat162 p1 = __floats2bfloat162_rn(oacc[ni][2], oacc[ni][3]);
        *(__nv_bfloat162*)&g_Obf[(size_t)(s*Tc + qg0)*Dc + h*HDc + col] = p0;
        *(__nv_bfloat162*)&g_Obf[(size_t)(s*Tc + qg1)*Dc + h*HDc + col] = p1;
    }
}

// ---------------- K4b: LN2(h2) -> h3(bf16) ; seed ysum = sum(h2) ------------
__global__ __launch_bounds__(128) void k4b_add_ln(
        const float* __restrict__ gamma2,
        const float* __restrict__ beta2) {
    const int warp = threadIdx.x >> 5, lane = threadIdx.x & 31;
    const int row = blockIdx.x*4 + warp;
    const int d0 = lane*4;
    size_t base = (size_t)row*Dc + d0;

    float4 hc = *(const float4*)&g_y[base];   // g_y holds h2
    float h2[4] = {hc.x, hc.y, hc.z, hc.w};

    float tot = warp_sum(h2[0]+h2[1]+h2[2]+h2[3]);
    float mean = tot * (1.f/Dc);
    float dv[4], vs = 0.f;
    #pragma unroll
    for (int i=0;i<4;i++) { dv[i] = h2[i]-mean; vs += dv[i]*dv[i]; }
    float var = warp_sum(vs) * (1.f/Dc);
    float rstd = rsqrtf(var + 1e-5f);

    float4 g4 = *(const float4*)&gamma2[d0];
    float4 b4 = *(const float4*)&beta2[d0];
    __nv_bfloat162 hb[2];
    hb[0] = __floats2bfloat162_rn(dv[0]*rstd*g4.x + b4.x, dv[1]*rstd*g4.y + b4.y);
    hb[1] = __floats2bfloat162_rn(dv[2]*rstd*g4.z + b4.z, dv[3]*rstd*g4.w + b4.w);
    *(uint2*)&g_h3bf[base] = *(uint2*)hb;
    if (lane == 0) g_ysum[row] = tot;
}

// ---------------- K7: final combine ----------------
__global__ void k7_final(const float* __restrict__ x,
                         const float* __restrict__ W_in,
                         const float* __restrict__ b_in,
                         const float* __restrict__ W_out,
                         const float* __restrict__ b_out,
                         float* __restrict__ out) {
    __shared__ float xs[Fc];
    __shared__ float xw[Dc];
    int bt = blockIdx.x;               // b*T + t
    int tid = threadIdx.x;             // 128
    if (tid < Fc) xs[tid] = x[bt*Fc + tid];
    __syncthreads();
    float acc = b_in[tid];
    #pragma unroll
    for (int f=0; f<Fc; f++) acc += xs[f]*W_in[tid*Fc + f];
    xw[tid] = acc;
    __syncthreads();
    if (tid < Fc) {
        float yp = b_out[tid];
        for (int dd=0; dd<Dc; dd++) yp += xw[dd]*W_out[tid*Dc + dd];
        int b = bt >> 9, t = bt & (Tc-1);
        int srow = (b*Fc + tid)*Tc + t;
        float ymean = (g_ysum[srow] + g_b2sum) * (1.f/(float)Dc);
        out[bt*Fc + tid] = xs[tid] + ymean + yp;
    }
}

// ---------------- launcher ----------------
extern "C" void kernel_launch(void* const* d_in, const int* in_sizes, int n_in,
                              void* d_out, int out_size) {
    const float* x      = (const float*)d_in[0];
    const float* W_in   = (const float*)d_in[1];
    const float* b_in   = (const float*)d_in[2];
    const float* gamma1 = (const float*)d_in[3];
    const float* beta1  = (const float*)d_in[4];
    const float* gamma2 = (const float*)d_in[5];
    const float* beta2  = (const float*)d_in[6];
    const float* W_qkv  = (const float*)d_in[7];
    const float* b_qkv  = (const float*)d_in[8];
    const float* W_o    = (const float*)d_in[9];
    const float* b_o    = (const float*)d_in[10];
    const float* W1     = (const float*)d_in[11];
    const float* b1     = (const float*)d_in[12];
    const float* W2     = (const float*)d_in[13];
    const float* b2     = (const float*)d_in[14];
    const float* W_out  = (const float*)d_in[15];
    const float* b_out  = (const float*)d_in[16];
    float* out = (float*)d_out;

    float *p_hcf, *p_y, *p_ysum, *p_w2sum;
    __nv_bfloat16 *p_h1bf, *p_qkbf, *p_QKo, *p_Vbf, *p_Obf, *p_h3bf;
    __nv_bfloat16 *p_Wqkv, *p_Wo, *p_W1;
    cudaGetSymbolAddress((void**)&p_hcf,  g_hcf);
    cudaGetSymbolAddress((void**)&p_y,    g_y);
    cudaGetSymbolAddress((void**)&p_ysum, g_ysum);
    cudaGetSymbolAddress((void**)&p_w2sum,g_w2sum);
    cudaGetSymbolAddress((void**)&p_h1bf, g_h1bf);
    cudaGetSymbolAddress((void**)&p_qkbf, g_qkbf);
    cudaGetSymbolAddress((void**)&p_QKo,  g_QKo);
    cudaGetSymbolAddress((void**)&p_Vbf,  g_Vbf);
    cudaGetSymbolAddress((void**)&p_Obf,  g_Obf);
    cudaGetSymbolAddress((void**)&p_h3bf, g_h3bf);
    cudaGetSymbolAddress((void**)&p_Wqkv, g_Wqkv_bf);
    cudaGetSymbolAddress((void**)&p_Wo,   g_Wo_bf);
    cudaGetSymbolAddress((void**)&p_W1,   g_W1_bf);

    // 0) weights -> bf16 ; w2sum/b2sum
    conv_weights<<<(HIDc*Dc + 255)/256, 256>>>(W_qkv, W_o, W1, W2, b2);
    // 1) hcf + LN1 + RoPE
    k1_hcf_ln_rope<<<ROWS/4, 128>>>(x, W_in, b_in, gamma1, beta1);
    // 2) Q,K -> bf16   (N=256)
    gemm_bf16<3><<<dim3(4, ROWS/128), 256>>>(p_qkbf, p_Wqkv, b_qkv, nullptr, p_QKo, ROWS, 256, 128, nullptr, nullptr, nullptr);
    // 3) V -> bf16     (N=128)
    gemm_bf16<3><<<dim3(2, ROWS/128), 256>>>(p_h1bf, p_Wqkv + 2*Dc*Dc, b_qkv + 2*Dc, nullptr, p_Vbf, ROWS, 128, 128, nullptr, nullptr, nullptr);
    // 4) attention (merged qtile pairs, 2048 blocks)
    attn_mma<<<dim3(Tc/128, NHc, Sc), 256>>>();
    // 5) h2 = O @ W_o^T + b_o + hcf  (fp32, residual fused)
    gemm_bf16<4><<<dim3(2, ROWS/128), 256>>>(p_Obf, p_Wo, b_o, p_y, nullptr, ROWS, 128, 128, nullptr, nullptr, p_hcf);
    // 6) LN2(h2) -> h3 (bf16), seed ysum = sum(h2)
    k4b_add_ln<<<ROWS/4, 128>>>(gamma2, beta2);
    // 7) FFN fused: ysum += rowsum(gelu(h3@W1^T+b1) * w2sum)   (N=512)
    gemm_bf16<1><<<dim3(8, ROWS/128), 256>>>(p_h3bf, p_W1, b1, nullptr, nullptr, ROWS, 512, 128, p_ysum, p_w2sum, nullptr);
    // 8) final combine (adds b2sum)
    k7_final<<<Bc*Tc, 128>>>(x, W_in, b_in, W_out, b_out, out);
}